// round 2
// baseline (speedup 1.0000x reference)
#include <cuda_runtime.h>
#include <math.h>

#define NUM_NODES   8192
#define MEME_DIM    64
#define VISION      2048
#define K_IN        32
#define VOCAB_N     256
#define G_TOT       (NUM_NODES * MEME_DIM)
#define TILE_FLOATS (MEME_DIM * VOCAB_N)   // 16384 floats = 64KB

// Scratch (device globals; no allocation allowed)
__device__ float  d_g_raw[G_TOT];
__device__ float2 d_partials[NUM_NODES];
__device__ float  d_stats[2];  // [0]=mean, [1]=inv_std

// ---------------------------------------------------------------------------
// Kernel 1: per-node gather + mean over K=32 inputs; per-block sum/sumsq partials
// ---------------------------------------------------------------------------
__global__ __launch_bounds__(256) void gather_kernel(
    const float* __restrict__ x,          // [2048, 64]
    const float* __restrict__ memes,      // [8192, 64]
    const int*   __restrict__ idx)        // [8192, 32]
{
    const int n   = blockIdx.x;
    const int tid = threadIdx.x;
    const int e   = tid & 63;
    const int kb  = tid >> 6;   // 0..3

    const int* row_idx = idx + n * K_IN;

    float acc = 0.f;
#pragma unroll
    for (int j = 0; j < 8; j++) {
        int r = __ldg(row_idx + kb + 4 * j);
        const float* src = (r < VISION) ? (x + (size_t)r * MEME_DIM)
                                        : (memes + (size_t)(r - VISION) * MEME_DIM);
        acc += __ldg(src + e);
    }

    __shared__ float red[256];
    red[tid] = acc;
    __syncthreads();

    float g = 0.f;
    if (tid < 64) {
        g = (red[tid] + red[tid + 64] + red[tid + 128] + red[tid + 192]) * (1.f / 32.f);
        d_g_raw[n * MEME_DIM + e] = g;
    }

    // block reduce sum & sumsq of the 64 g values (other threads contribute 0)
    float s = (tid < 64) ? g : 0.f;
    float q = s * s;
    const int lane = tid & 31, w = tid >> 5;
#pragma unroll
    for (int o = 16; o > 0; o >>= 1) {
        s += __shfl_down_sync(0xffffffffu, s, o);
        q += __shfl_down_sync(0xffffffffu, q, o);
    }
    __shared__ float ws[8], wq[8];
    if (lane == 0) { ws[w] = s; wq[w] = q; }
    __syncthreads();
    if (tid == 0) {
        float S = 0.f, Q = 0.f;
#pragma unroll
        for (int i = 0; i < 8; i++) { S += ws[i]; Q += wq[i]; }
        d_partials[n] = make_float2(S, Q);
    }
}

// ---------------------------------------------------------------------------
// Kernel 2: reduce partials -> global mean / inv_std (ddof=1), deterministic
// ---------------------------------------------------------------------------
__global__ __launch_bounds__(256) void stats_kernel()
{
    __shared__ double ssum[256], ssq[256];
    const int tid = threadIdx.x;
    double s = 0.0, q = 0.0;
    for (int i = tid; i < NUM_NODES; i += 256) {
        float2 p = d_partials[i];
        s += (double)p.x;
        q += (double)p.y;
    }
    ssum[tid] = s; ssq[tid] = q;
    __syncthreads();
    for (int st = 128; st > 0; st >>= 1) {
        if (tid < st) { ssum[tid] += ssum[tid + st]; ssq[tid] += ssq[tid + st]; }
        __syncthreads();
    }
    if (tid == 0) {
        const double N = (double)G_TOT;
        double mean = ssum[0] / N;
        double var  = (ssq[0] - ssum[0] * ssum[0] / N) / (N - 1.0);
        d_stats[0] = (float)mean;
        d_stats[1] = (float)(1.0 / sqrt(var));
    }
}

// ---------------------------------------------------------------------------
// Kernel 3: fused remix. One node per CTA. vocab[n] tile loaded into smem once.
// ---------------------------------------------------------------------------
__global__ __launch_bounds__(256) void remix_kernel(
    const float* __restrict__ vocab,       // [8192, 64, 256]
    const float* __restrict__ raw_sc,      // [1]
    const float* __restrict__ raw_sh,      // [1]
    float*       __restrict__ out)         // [8192, 64]
{
    extern __shared__ float smem[];
    float* vs = smem;                       // 16384 floats: vocab tile [64][256]
    float* gs = smem + TILE_FLOATS;         // 64 floats: standardized g row
    float* fs = gs + MEME_DIM;              // 256 floats: fractions

    const int n    = blockIdx.x;
    const int tid  = threadIdx.x;
    const int lane = tid & 31, w = tid >> 5;

    // standardized g row
    if (tid < MEME_DIM) {
        float mean = d_stats[0], istd = d_stats[1];
        gs[tid] = (d_g_raw[n * MEME_DIM + tid] - mean) * istd;
    }

    // load vocab tile (64KB), float4 coalesced
    {
        const float4* vsrc = (const float4*)(vocab + (size_t)n * TILE_FLOATS);
        float4* vdst = (float4*)vs;
#pragma unroll
        for (int i = 0; i < 16; i++)
            vdst[tid + 256 * i] = __ldg(vsrc + tid + 256 * i);
    }
    __syncthreads();

    // dot products: thread tid owns vocab column v = tid
    float acc = 0.f;
#pragma unroll
    for (int e = 0; e < MEME_DIM; e++)
        acc = fmaf(gs[e], vs[e * VOCAB_N + tid], acc);

    // block reduce sum & sumsq over 256 dot values
    __shared__ float wsum[8], wsq[8];
    {
        float s = acc, q = acc * acc;
#pragma unroll
        for (int o = 16; o > 0; o >>= 1) {
            s += __shfl_down_sync(0xffffffffu, s, o);
            q += __shfl_down_sync(0xffffffffu, q, o);
        }
        if (lane == 0) { wsum[w] = s; wsq[w] = q; }
    }
    __syncthreads();
    float bsum = 0.f, bsq = 0.f;
#pragma unroll
    for (int i = 0; i < 8; i++) { bsum += wsum[i]; bsq += wsq[i]; }

    const float m   = bsum * (1.f / 256.f);
    float var = (bsq - bsum * bsum * (1.f / 256.f)) * (1.f / 255.f);
    var = fmaxf(var, 0.f);
    const float sd  = sqrtf(var) + 0.001f;

    const float sc   = expf(__ldg(raw_sc));   // soft_clip
    const float lnsh = __ldg(raw_sh);         // ln(sharpness) == raw_sharpness

    float d = (acc - m) / sd;
    d = tanhf(d / sc) * sc;
    float p = expf(d * lnsh);

    // block reduce sum of p
    __syncthreads();  // protect wsum reuse
    {
        float s = p;
#pragma unroll
        for (int o = 16; o > 0; o >>= 1)
            s += __shfl_down_sync(0xffffffffu, s, o);
        if (lane == 0) wsum[w] = s;
    }
    __syncthreads();
    float psum = 0.f;
#pragma unroll
    for (int i = 0; i < 8; i++) psum += wsum[i];

    fs[tid] = p / (psum + 0.001f);
    __syncthreads();

    // output GEMV: warp w handles e rows {8w .. 8w+7}; lanes stride v, conflict-free
#pragma unroll
    for (int r = 0; r < 8; r++) {
        const int e = w * 8 + r;
        float a = 0.f;
#pragma unroll
        for (int c = 0; c < 8; c++) {
            const int v = lane + 32 * c;
            a = fmaf(vs[e * VOCAB_N + v], fs[v], a);
        }
#pragma unroll
        for (int o = 16; o > 0; o >>= 1)
            a += __shfl_down_sync(0xffffffffu, a, o);
        if (lane == 0) out[(size_t)n * MEME_DIM + e] = a;
    }
}

// ---------------------------------------------------------------------------
extern "C" void kernel_launch(void* const* d_in, const int* in_sizes, int n_in,
                              void* d_out, int out_size)
{
    const float* x      = (const float*)d_in[0];   // [2048, 64]
    const float* memes  = (const float*)d_in[1];   // [8192, 64]
    const int*   idx    = (const int*)  d_in[2];   // [8192, 32]
    const float* vocab  = (const float*)d_in[3];   // [8192, 64, 256]
    const float* raw_sc = (const float*)d_in[4];   // [1]
    const float* raw_sh = (const float*)d_in[5];   // [1]
    float* out = (float*)d_out;

    const int smem_bytes = (TILE_FLOATS + MEME_DIM + VOCAB_N) * sizeof(float); // 66816
    cudaFuncSetAttribute(remix_kernel, cudaFuncAttributeMaxDynamicSharedMemorySize, smem_bytes);

    gather_kernel<<<NUM_NODES, 256>>>(x, memes, idx);
    stats_kernel<<<1, 256>>>();
    remix_kernel<<<NUM_NODES, 256, smem_bytes>>>(vocab, raw_sc, raw_sh, out);
}